// round 8
// baseline (speedup 1.0000x reference)
#include <cuda_runtime.h>
#include <cstdint>
#include <cstddef>

#define BATCH 2
#define NPTS  8192
#define SPTS  1024
#define NSAMP 32
#define VNUM  8
#define CFEAT 64
#define CIN   70
#define COUT  128
#define HID1  32
#define NQ     (BATCH*SPTS)        /* 2048  */
#define NITEMS (NQ*NSAMP)          /* 65536 */

// ---------------- static device scratch ----------------
__device__ __align__(16) float g_newxyz[NQ*3];
__device__ __align__(16) int   g_gidx[NITEMS];
__device__ __align__(16) float g_gf [NITEMS*CIN];   // 18.3 MB
__device__ __align__(16) float g_gf2[NITEMS*CIN];   // 18.3 MB
__device__ __align__(16) float g_w  [NITEMS*COUT];  // 33.5 MB
__device__ double g_stats1[2*HID1];
__device__ double g_stats2[2*COUT];
__device__ float  g_bn1[2*HID1];
__device__ float  g_bn2[2*COUT];

__device__ __forceinline__ float gelu_exact(float x){
    return 0.5f * x * (1.0f + erff(x * 0.70710678118654752440f));
}

// ---------------- kernel 0: zero stats ----------------
__global__ void zero_stats_kernel(){
    int t = threadIdx.x;
    if (t < 2*HID1) g_stats1[t] = 0.0;
    g_stats2[t] = 0.0;               // blockDim = 256 = 2*COUT
}

// ---------------- kernel 1: farthest point sampling ----------------
// One block per batch. Bitwise-exact vs eager JAX: ((dx*dx+dy*dy)+dz*dz) with
// round-to-nearest mul/add (no FMA), fminf, first-index argmax.
__global__ void __launch_bounds__(1024) fps_kernel(const float* __restrict__ xyz,
                                                   float* __restrict__ out_tail,
                                                   int write_tail){
    int b = blockIdx.x;
    extern __shared__ float sm[];
    float* sx = sm;
    float* sy = sm + NPTS;
    float* sz = sm + 2*NPTS;
    float* rv = sm + 3*NPTS;        // 32
    int*   ri = (int*)(rv + 32);    // 32
    __shared__ int slast;

    const float* xb = xyz + (size_t)b * NPTS * 3;
    for (int i = threadIdx.x; i < NPTS; i += 1024){
        sx[i] = xb[3*i]; sy[i] = xb[3*i+1]; sz[i] = xb[3*i+2];
    }
    __syncthreads();

    float dmin[8];
    #pragma unroll
    for (int k = 0; k < 8; k++) dmin[k] = __int_as_float(0x7f800000);
    int last = 0;
    int lane = threadIdx.x & 31, warp = threadIdx.x >> 5;

    for (int s = 0; s < SPTS; s++){
        float px = sx[last], py = sy[last], pz = sz[last];   // smem broadcast
        if (threadIdx.x == 0){
            int o = (b*SPTS + s)*3;
            g_newxyz[o] = px; g_newxyz[o+1] = py; g_newxyz[o+2] = pz;
            if (write_tail){ out_tail[o] = px; out_tail[o+1] = py; out_tail[o+2] = pz; }
        }
        float bv = -1.0f; int bi = 0;
        #pragma unroll
        for (int k = 0; k < 8; k++){
            int n = threadIdx.x + (k << 10);
            float dx = sx[n] - px;
            float dy = sy[n] - py;
            float dz = sz[n] - pz;
            float d = __fadd_rn(__fadd_rn(__fmul_rn(dx,dx), __fmul_rn(dy,dy)), __fmul_rn(dz,dz));
            float dm = fminf(dmin[k], d);
            dmin[k] = dm;
            if (dm > bv){ bv = dm; bi = n; }        // strict > keeps lowest n per thread
        }
        #pragma unroll
        for (int off = 16; off; off >>= 1){
            float ov = __shfl_down_sync(0xffffffffu, bv, off);
            int   oi = __shfl_down_sync(0xffffffffu, bi, off);
            if (ov > bv || (ov == bv && oi < bi)){ bv = ov; bi = oi; }
        }
        if (lane == 0){ rv[warp] = bv; ri[warp] = bi; }
        __syncthreads();
        if (warp == 0){
            bv = rv[lane]; bi = ri[lane];
            #pragma unroll
            for (int off = 16; off; off >>= 1){
                float ov = __shfl_down_sync(0xffffffffu, bv, off);
                int   oi = __shfl_down_sync(0xffffffffu, bi, off);
                if (ov > bv || (ov == bv && oi < bi)){ bv = ov; bi = oi; }
            }
            if (lane == 0) slast = bi;
        }
        __syncthreads();
        last = slast;
    }
}

// ---------------- kernel 2: ball query (first NSAMP in index order) ----------------
__global__ void ballquery_kernel(const float* __restrict__ xyz){
    int q = blockIdx.x * 8 + (threadIdx.x >> 5);
    if (q >= NQ) return;
    int lane = threadIdx.x & 31;
    int b = q >> 10;
    const float* xb = xyz + (size_t)b * NPTS * 3;
    float qx = g_newxyz[q*3], qy = g_newxyz[q*3+1], qz = g_newxyz[q*3+2];
    int* g = g_gidx + q*NSAMP;
    const float RR = 0.04f;   // f32(0.2*0.2 in double) == f32 nearest to 0.04
    int count = 0;
    for (int base = 0; base < NPTS; base += 32){
        int n = base + lane;
        float dx = xb[3*n] - qx, dy = xb[3*n+1] - qy, dz = xb[3*n+2] - qz;
        float d = __fadd_rn(__fadd_rn(__fmul_rn(dx,dx), __fmul_rn(dy,dy)), __fmul_rn(dz,dz));
        bool w = d < RR;
        unsigned m = __ballot_sync(0xffffffffu, w);
        if (w){
            int slot = count + __popc(m & ((1u << lane) - 1u));
            if (slot < NSAMP) g[slot] = n;
        }
        count += __popc(m);
        if (count >= NSAMP) break;
    }
    int rem = min(count, NSAMP);
    if (lane >= rem) g[lane] = -1;
}

// ---------------- kernel 3: BN1 stats over pre-activation of MLP1 layer 0 ----------------
__global__ void __launch_bounds__(256) stats1_kernel(const float* __restrict__ xyz,
                                                     const int* __restrict__ mc_idx,
                                                     const float* __restrict__ W1_0,
                                                     const float* __restrict__ b1_0){
    __shared__ float sW[HID1*13], sb[HID1], smc[VNUM*3];
    __shared__ float part[8][2*HID1];
    int tid = threadIdx.x;
    int item = blockIdx.x*256 + tid;
    int b = item >> 15;                       // 32768 items per batch, blocks don't straddle
    for (int i = tid; i < HID1*13; i += 256) sW[i] = W1_0[i];
    if (tid < HID1) sb[tid] = b1_0[tid];
    if (tid < VNUM*3){
        int v = tid/3, c = tid - v*3;
        smc[tid] = xyz[(size_t)b*NPTS*3 + (size_t)mc_idx[v]*3 + c];
    }
    __syncthreads();

    float sum[HID1], sq[HID1];
    #pragma unroll
    for (int o = 0; o < HID1; o++){ sum[o] = 0.f; sq[o] = 0.f; }

    int gi = g_gidx[item];
    float gx = 0.f, gy = 0.f, gz = 0.f;
    if (gi >= 0){
        const float* p = xyz + (size_t)b*NPTS*3 + (size_t)gi*3;
        gx = p[0]; gy = p[1]; gz = p[2];
    }
    for (int v = 0; v < VNUM; v++){
        float mx = smc[v*3], my = smc[v*3+1], mz = smc[v*3+2];
        float a0 = gx - mx, a1 = gy - my, a2 = gz - mz;
        float eu = sqrtf(a0*a0 + a1*a1 + a2*a2);
        float rel[13] = {-a0,-a1,-a2, a0,a1,a2, eu, gx,gy,gz, mx,my,mz};
        #pragma unroll
        for (int o = 0; o < HID1; o++){
            float a = sb[o];
            #pragma unroll
            for (int i = 0; i < 13; i++) a += rel[i] * sW[o*13+i];
            sum[o] += a; sq[o] += a*a;
        }
    }
    #pragma unroll
    for (int off = 16; off; off >>= 1){
        #pragma unroll
        for (int o = 0; o < HID1; o++){
            sum[o] += __shfl_down_sync(0xffffffffu, sum[o], off);
            sq[o]  += __shfl_down_sync(0xffffffffu, sq[o],  off);
        }
    }
    if ((tid & 31) == 0){
        int w = tid >> 5;
        #pragma unroll
        for (int o = 0; o < HID1; o++){ part[w][o] = sum[o]; part[w][HID1+o] = sq[o]; }
    }
    __syncthreads();
    if (tid < 2*HID1){
        float acc = 0.f;
        #pragma unroll
        for (int w = 0; w < 8; w++) acc += part[w][tid];
        atomicAdd(&g_stats1[tid], (double)acc);
    }
}

__global__ void finalize_bn1(const float* __restrict__ g1, const float* __restrict__ be1){
    int o = threadIdx.x;
    if (o < HID1){
        double n = (double)NITEMS * (double)VNUM;
        double m = g_stats1[o] / n;
        double var = g_stats1[HID1+o] / n - m*m;
        double sc = (double)g1[o] / sqrt(var + 1e-5);
        g_bn1[o] = (float)sc;
        g_bn1[HID1+o] = (float)((double)be1[o] - m*sc);
    }
}

// ---------------- kernel 4: fused main (gf, MLP1, gumbel-softmax, gf2) ----------------
// smem float offsets
#define M1_W10  0      /* 416  */
#define M1_B10  416    /* 32   */
#define M1_SC   448    /* 32   */
#define M1_SH   480    /* 32   */
#define M1_W11  512    /* 2240 */
#define M1_B11  2752   /* 70   */
#define M1_GF   2824   /* 2240 */
#define M1_GX   5064   /* 96   */
#define M1_MC   5160   /* 24   */
#define M1_NEW  5184   /* 3    */
#define M1_GI   5188   /* 32 ints */
#define M1_A2   5220   /* 256*71 = 18176 */
#define M1_TOT  23396

__global__ void __launch_bounds__(256) main1_kernel(const float* __restrict__ xyz,
                                                    const float* __restrict__ f,
                                                    const int* __restrict__ mc_idx,
                                                    const float* __restrict__ gumbel,
                                                    const float* __restrict__ W1_0,
                                                    const float* __restrict__ b1_0,
                                                    const float* __restrict__ W1_1,
                                                    const float* __restrict__ b1_1){
    extern __shared__ float sm[];
    float* sW10 = sm + M1_W10;
    float* sb10 = sm + M1_B10;
    float* ssc  = sm + M1_SC;
    float* ssh  = sm + M1_SH;
    float* sW11 = sm + M1_W11;
    float* sb11 = sm + M1_B11;
    float* sgf  = sm + M1_GF;
    float* sgx  = sm + M1_GX;
    float* smc  = sm + M1_MC;
    float* snew = sm + M1_NEW;
    int*   sgi  = (int*)(sm + M1_GI);
    float* sa2  = sm + M1_A2;

    int tid = threadIdx.x;
    int bs  = blockIdx.x;
    int b   = bs >> 10;

    for (int i = tid; i < HID1*13; i += 256) sW10[i] = W1_0[i];
    for (int i = tid; i < CIN*HID1; i += 256) sW11[i] = W1_1[i];
    if (tid < 32){ sb10[tid] = b1_0[tid]; ssc[tid] = g_bn1[tid]; ssh[tid] = g_bn1[32+tid]; }
    if (tid >= 64 && tid < 64+CIN) sb11[tid-64] = b1_1[tid-64];
    if (tid >= 160 && tid < 192) sgi[tid-160] = g_gidx[bs*NSAMP + tid-160];
    if (tid >= 192 && tid < 195) snew[tid-192] = g_newxyz[bs*3 + tid-192];
    if (tid >= 200 && tid < 224){
        int j = tid - 200; int v = j/3, c = j - v*3;
        smc[j] = xyz[(size_t)b*NPTS*3 + (size_t)mc_idx[v]*3 + c];
    }
    __syncthreads();

    if (tid < 96){
        int n = tid/3, c = tid - n*3;
        int gi = sgi[n];
        sgx[tid] = (gi < 0) ? 0.0f : xyz[(size_t)b*NPTS*3 + (size_t)gi*3 + c];
    }
    __syncthreads();

    // build gf tile (smem + global)
    for (int idx = tid; idx < NSAMP*CIN; idx += 256){
        int n = idx / CIN, c = idx - n*CIN;
        int gi = sgi[n];
        float val;
        if (c < 3)      val = sgx[n*3 + c];
        else if (c < 6) val = sgx[n*3 + c - 3] - snew[c-3];   // masked: 0 - new = -new (matches ref)
        else            val = (gi < 0) ? 0.0f : f[((size_t)b*NPTS + (size_t)gi)*CFEAT + (c-6)];
        sgf[idx] = val;
        g_gf[(size_t)bs*(NSAMP*CIN) + idx] = val;
    }
    __syncthreads();

    // phase C: one thread per (n,v) -> a2 row, stride-71 tile (conflict-free)
    {
        int n = tid >> 3, v = tid & 7;
        float gx = sgx[n*3], gy = sgx[n*3+1], gz = sgx[n*3+2];
        float mx = smc[v*3], my = smc[v*3+1], mz = smc[v*3+2];
        float a0 = gx-mx, a1 = gy-my, a2v = gz-mz;
        float eu = sqrtf(a0*a0 + a1*a1 + a2v*a2v);
        float rel[13] = {-a0,-a1,-a2v, a0,a1,a2v, eu, gx,gy,gz, mx,my,mz};
        float h[HID1];
        #pragma unroll
        for (int o = 0; o < HID1; o++){
            float a = sb10[o];
            #pragma unroll
            for (int i = 0; i < 13; i++) a += rel[i] * sW10[o*13+i];
            a = a * ssc[o] + ssh[o];
            h[o] = gelu_exact(a);
        }
        for (int c = 0; c < CIN; c++){
            float acc = sb11[c];
            #pragma unroll
            for (int hh = 0; hh < HID1; hh++) acc += h[hh] * sW11[c*HID1 + hh];
            sa2[tid*71 + c] = acc;
        }
    }
    __syncthreads();

    // phase D: gumbel softmax over V, aggregate, write gf2
    for (int idx = tid; idx < NSAMP*CIN; idx += 256){
        int n = idx / CIN, c = idx - n*CIN;
        float gfv = sgf[idx];
        int base = n*8*71 + c;
        float p[8];
        #pragma unroll
        for (int v = 0; v < 8; v++) p[v] = gfv * sa2[base + v*71];
        const float4* gp = reinterpret_cast<const float4*>(gumbel + ((size_t)bs*(NSAMP*CIN) + idx)*8);
        float4 u0 = gp[0], u1 = gp[1];
        float uu[8] = {u0.x,u0.y,u0.z,u0.w,u1.x,u1.y,u1.z,u1.w};
        float x[8];
        float mx = __int_as_float(0xff800000);
        #pragma unroll
        for (int v = 0; v < 8; v++){
            float gn = -logf(-logf(uu[v]));
            x[v] = p[v] + gn;
            mx = fmaxf(mx, x[v]);
        }
        float se = 0.f, num = 0.f;
        #pragma unroll
        for (int v = 0; v < 8; v++){
            float e = expf(x[v] - mx);
            se += e; num += e * p[v];
        }
        float agg = num / se;
        float outv = (sgi[n] < 0) ? 0.0f : (agg + gfv);
        g_gf2[(size_t)bs*(NSAMP*CIN) + idx] = outv;
    }
}

// ---------------- kernel 5: w_pre = gf2 @ W2_0^T + b2_0  (+ BN2 stats) ----------------
#define K5_GF2 0                    /* 64*71 = 4544 */
#define K5_WT  4544                 /* 70*132 = 9240, 16B aligned (4544*4=18176) */
#define K5_SUM 13784                /* 128 */
#define K5_SQ  13912                /* 128 */
#define K5_TOT 14040

__global__ void __launch_bounds__(256) w_stats_kernel(const float* __restrict__ W2_0,
                                                      const float* __restrict__ b2_0){
    extern __shared__ float sm[];
    float* sG  = sm + K5_GF2;
    float* sWt = sm + K5_WT;
    float* ssum = sm + K5_SUM;
    float* ssq  = sm + K5_SQ;
    int tid = threadIdx.x;
    int row0 = blockIdx.x * 64;

    for (int idx = tid; idx < COUT*CIN; idx += 256){
        int o = idx / CIN, i = idx - o*CIN;
        sWt[i*132 + o] = W2_0[idx];
    }
    for (int idx = tid; idx < 64*CIN; idx += 256){
        int r = idx / CIN, i = idx - r*CIN;
        sG[r*71 + i] = g_gf2[(size_t)row0*CIN + idx];
    }
    if (tid < 128){ ssum[tid] = 0.f; ssq[tid] = 0.f; }
    __syncthreads();

    int rt = tid >> 5, ct = tid & 31;
    float acc[8][4];
    #pragma unroll
    for (int r = 0; r < 8; r++)
        #pragma unroll
        for (int c = 0; c < 4; c++) acc[r][c] = 0.f;

    for (int k = 0; k < CIN; k++){
        float4 w = *reinterpret_cast<const float4*>(&sWt[k*132 + ct*4]);
        #pragma unroll
        for (int r = 0; r < 8; r++){
            float g = sG[(rt*8 + r)*71 + k];
            acc[r][0] += g * w.x; acc[r][1] += g * w.y;
            acc[r][2] += g * w.z; acc[r][3] += g * w.w;
        }
    }
    float4 bb = *reinterpret_cast<const float4*>(&b2_0[ct*4]);
    float bias[4] = {bb.x, bb.y, bb.z, bb.w};
    float s[4] = {0,0,0,0}, q[4] = {0,0,0,0};
    #pragma unroll
    for (int r = 0; r < 8; r++){
        #pragma unroll
        for (int c = 0; c < 4; c++){
            acc[r][c] += bias[c];
            s[c] += acc[r][c];
            q[c] += acc[r][c]*acc[r][c];
        }
        float4 o4 = make_float4(acc[r][0], acc[r][1], acc[r][2], acc[r][3]);
        *reinterpret_cast<float4*>(&g_w[((size_t)row0 + rt*8 + r)*COUT + ct*4]) = o4;
    }
    #pragma unroll
    for (int c = 0; c < 4; c++){
        atomicAdd(&ssum[ct*4 + c], s[c]);
        atomicAdd(&ssq [ct*4 + c], q[c]);
    }
    __syncthreads();
    if (tid < 128){
        atomicAdd(&g_stats2[tid],      (double)ssum[tid]);
        atomicAdd(&g_stats2[128+tid],  (double)ssq[tid]);
    }
}

__global__ void finalize_bn2(const float* __restrict__ g2, const float* __restrict__ be2){
    int o = threadIdx.x;
    if (o < COUT){
        double n = (double)NITEMS;
        double m = g_stats2[o] / n;
        double var = g_stats2[COUT+o] / n - m*m;
        double sc = (double)g2[o] / sqrt(var + 1e-5);
        g_bn2[o] = (float)sc;
        g_bn2[COUT+o] = (float)((double)be2[o] - m*sc);
    }
}

// ---------------- kernel 6: final fused GEMM (K=198) + gelu + max/sum reduce ----------------
#define F_W2T  0                    /* 128*132 = 16896 */
#define F_WRT  16896                /* 70*132 = 9240 (16896*4 % 16 == 0) */
#define F_H    26136                /* 32*128 = 4096 */
#define F_GF   30232                /* 32*71  = 2272 */
#define F_BN   32504                /* 256 */
#define F_RM   32760                /* 8*128 = 1024 */
#define F_RS   33784                /* 8*128 = 1024 */
#define F_TOT  34808

__global__ void __launch_bounds__(256) final_kernel(const float* __restrict__ W2_1,
                                                    const float* __restrict__ b2_1,
                                                    const float* __restrict__ Wr,
                                                    const float* __restrict__ br,
                                                    float* __restrict__ out){
    extern __shared__ float sm[];
    float* sW2t = sm + F_W2T;
    float* sWrt = sm + F_WRT;
    float* sh   = sm + F_H;
    float* sgf  = sm + F_GF;
    float* sbn  = sm + F_BN;
    float* srm  = sm + F_RM;
    float* srs  = sm + F_RS;
    int tid = threadIdx.x;

    for (int idx = tid; idx < COUT*COUT; idx += 256){
        int o = idx >> 7, k = idx & 127;
        sW2t[k*132 + o] = W2_1[idx];
    }
    for (int idx = tid; idx < COUT*CIN; idx += 256){
        int o = idx / CIN, i = idx - o*CIN;
        sWrt[i*132 + o] = Wr[idx];
    }
    if (tid < 256) sbn[tid] = g_bn2[tid];

    int rt = tid >> 5, ct = tid & 31;
    float4 b1v = *reinterpret_cast<const float4*>(&b2_1[ct*4]);
    float4 brv = *reinterpret_cast<const float4*>(&br[ct*4]);
    float bsum[4] = {b1v.x + brv.x, b1v.y + brv.y, b1v.z + brv.z, b1v.w + brv.w};

    for (int g = 0; g < 4; g++){
        int bs = blockIdx.x*4 + g;
        __syncthreads();   // weights ready (g=0) / previous group's reads done
        for (int idx = tid; idx < NSAMP*COUT; idx += 256){
            int o = idx & 127;
            float v = g_w[(size_t)bs*(NSAMP*COUT) + idx];
            sh[idx] = gelu_exact(v * sbn[o] + sbn[128+o]);
        }
        for (int idx = tid; idx < NSAMP*CIN; idx += 256){
            int r = idx / CIN, i = idx - r*CIN;
            sgf[r*71 + i] = g_gf[(size_t)bs*(NSAMP*CIN) + idx];
        }
        __syncthreads();

        float acc[4][4];
        #pragma unroll
        for (int r = 0; r < 4; r++)
            #pragma unroll
            for (int c = 0; c < 4; c++) acc[r][c] = bsum[c];

        for (int k = 0; k < COUT; k++){
            float4 w = *reinterpret_cast<const float4*>(&sW2t[k*132 + ct*4]);
            #pragma unroll
            for (int r = 0; r < 4; r++){
                float h = sh[(rt*4 + r)*COUT + k];
                acc[r][0] += h * w.x; acc[r][1] += h * w.y;
                acc[r][2] += h * w.z; acc[r][3] += h * w.w;
            }
        }
        for (int i = 0; i < CIN; i++){
            float4 w = *reinterpret_cast<const float4*>(&sWrt[i*132 + ct*4]);
            #pragma unroll
            for (int r = 0; r < 4; r++){
                float gv = sgf[(rt*4 + r)*71 + i];
                acc[r][0] += gv * w.x; acc[r][1] += gv * w.y;
                acc[r][2] += gv * w.z; acc[r][3] += gv * w.w;
            }
        }
        float mxv[4], smv[4];
        #pragma unroll
        for (int c = 0; c < 4; c++){ mxv[c] = __int_as_float(0xff800000); smv[c] = 0.f; }
        #pragma unroll
        for (int r = 0; r < 4; r++)
            #pragma unroll
            for (int c = 0; c < 4; c++){
                float nf = gelu_exact(acc[r][c]);
                mxv[c] = fmaxf(mxv[c], nf);
                smv[c] += nf;
            }
        #pragma unroll
        for (int c = 0; c < 4; c++){
            srm[rt*128 + ct*4 + c] = mxv[c];
            srs[rt*128 + ct*4 + c] = smv[c];
        }
        __syncthreads();
        if (tid < 128){
            float m = srm[tid], s = srs[tid];
            #pragma unroll
            for (int w = 1; w < 8; w++){
                m = fmaxf(m, srm[w*128 + tid]);
                s += srs[w*128 + tid];
            }
            out[(size_t)bs*COUT + tid] = m + s;
        }
    }
}

// ---------------- launch ----------------
extern "C" void kernel_launch(void* const* d_in, const int* in_sizes, int n_in,
                              void* d_out, int out_size) {
    const float* xyz    = (const float*)d_in[0];
    const float* f      = (const float*)d_in[1];
    const int*   mc_idx = (const int*)  d_in[2];
    const float* gumbel = (const float*)d_in[3];
    const float* W1_0   = (const float*)d_in[4];
    const float* b1_0   = (const float*)d_in[5];
    const float* g1_0   = (const float*)d_in[6];
    const float* be1_0  = (const float*)d_in[7];
    const float* W1_1   = (const float*)d_in[8];
    const float* b1_1   = (const float*)d_in[9];
    const float* W2_0   = (const float*)d_in[10];
    const float* b2_0   = (const float*)d_in[11];
    const float* g2_0   = (const float*)d_in[12];
    const float* be2_0  = (const float*)d_in[13];
    const float* W2_1   = (const float*)d_in[14];
    const float* b2_1   = (const float*)d_in[15];
    const float* Wr     = (const float*)d_in[16];
    const float* br     = (const float*)d_in[17];
    float* out = (float*)d_out;

    const int fps_smem = (3*NPTS + 64) * 4;          // 98560
    const int m1_smem  = M1_TOT * 4;                 // 93584
    const int k5_smem  = K5_TOT * 4;                 // 56160
    const int fi_smem  = F_TOT * 4;                  // 139232
    cudaFuncSetAttribute(fps_kernel,    cudaFuncAttributeMaxDynamicSharedMemorySize, fps_smem);
    cudaFuncSetAttribute(main1_kernel,  cudaFuncAttributeMaxDynamicSharedMemorySize, m1_smem);
    cudaFuncSetAttribute(w_stats_kernel,cudaFuncAttributeMaxDynamicSharedMemorySize, k5_smem);
    cudaFuncSetAttribute(final_kernel,  cudaFuncAttributeMaxDynamicSharedMemorySize, fi_smem);

    int write_tail = (out_size >= NQ*COUT + NQ*3) ? 1 : 0;
    float* tail = out + (size_t)NQ*COUT;

    zero_stats_kernel<<<1, 256>>>();
    fps_kernel<<<BATCH, 1024, fps_smem>>>(xyz, tail, write_tail);
    ballquery_kernel<<<NQ/8, 256>>>(xyz);
    stats1_kernel<<<NITEMS/256, 256>>>(xyz, mc_idx, W1_0, b1_0);
    finalize_bn1<<<1, 32>>>(g1_0, be1_0);
    main1_kernel<<<NQ, 256, m1_smem>>>(xyz, f, mc_idx, gumbel, W1_0, b1_0, W1_1, b1_1);
    w_stats_kernel<<<NITEMS/64, 256, k5_smem>>>(W2_0, b2_0);
    finalize_bn2<<<1, 128>>>(g2_0, be2_0);
    final_kernel<<<NQ/4, 256, fi_smem>>>(W2_1, b2_1, Wr, br, out);
}

// round 9
// speedup vs baseline: 1.0263x; 1.0263x over previous
#include <cuda_runtime.h>
#include <cstdint>
#include <cstddef>

#define BATCH 2
#define NPTS  8192
#define SPTS  1024
#define NSAMP 32
#define VNUM  8
#define CFEAT 64
#define CIN   70
#define COUT  128
#define HID1  32
#define NQ     (BATCH*SPTS)        /* 2048  */
#define NITEMS (NQ*NSAMP)          /* 65536 */

// ---------------- static device scratch ----------------
__device__ __align__(16) float g_newxyz[NQ*3];
__device__ __align__(16) int   g_gidx[NITEMS];
__device__ __align__(16) float g_gf [NITEMS*CIN];   // 18.3 MB
__device__ __align__(16) float g_gf2[NITEMS*CIN];   // 18.3 MB
__device__ __align__(16) float g_w  [NITEMS*COUT];  // 33.5 MB
__device__ double g_q[35];          // q-moment sums (7 first + 28 second)
__device__ double g_stats2[2*COUT];
__device__ float  g_bn1[2*HID1];
__device__ float  g_bn2[2*COUT];

__device__ __forceinline__ float gelu_exact(float x){
    return 0.5f * x * (1.0f + erff(x * 0.70710678118654752440f));
}
__device__ __forceinline__ unsigned long long umax64(unsigned long long a, unsigned long long b){
    return a > b ? a : b;
}
// -log(u) with MUFU log, series-guarded near u=1 where MUFU absolute error
// would be large relative to the tiny result.
__device__ __forceinline__ float neglog_u(float u){
    float t = 1.0f - u;
    float y = -__logf(u);
    if (t < 0.0078125f) y = t*(1.0f + t*(0.5f + t*0.3333333333f));
    return y;
}

// ---------------- kernel 0: zero stats ----------------
__global__ void zero_stats_kernel(){
    int t = threadIdx.x;
    if (t < 35) g_q[t] = 0.0;
    g_stats2[t] = 0.0;               // blockDim = 256 = 2*COUT
}

// ---------------- kernel 1: farthest point sampling ----------------
// One block per batch. Points + dmin in registers; packed u64 argmax keys
// (value in high bits, 8191-idx in low 13 bits -> max == lowest-index tie-break);
// one barrier per step via parity-double-buffered partials.
__global__ void __launch_bounds__(1024) fps_kernel(const float* __restrict__ xyz,
                                                   float* __restrict__ out_tail,
                                                   int write_tail){
    int b = blockIdx.x;
    extern __shared__ float sm[];
    float* sx = sm;
    float* sy = sm + NPTS;
    float* sz = sm + 2*NPTS;
    unsigned long long* kv = (unsigned long long*)(sm + 3*NPTS);  // 2 x 32

    const float* xb = xyz + (size_t)b * NPTS * 3;
    int tid = threadIdx.x;
    for (int i = tid; i < NPTS; i += 1024){
        sx[i] = xb[3*i]; sy[i] = xb[3*i+1]; sz[i] = xb[3*i+2];
    }
    __syncthreads();

    float rx[8], ry[8], rz[8], dmin[8];
    #pragma unroll
    for (int k = 0; k < 8; k++){
        int n = tid + (k << 10);
        rx[k] = sx[n]; ry[k] = sy[n]; rz[k] = sz[n];
        dmin[k] = __int_as_float(0x7f800000);
    }
    int last = 0;
    int lane = tid & 31, warp = tid >> 5;
    int par = 0;

    for (int s = 0; s < SPTS; s++){
        float px = sx[last], py = sy[last], pz = sz[last];
        if (tid == 0){
            int o = (b*SPTS + s)*3;
            g_newxyz[o] = px; g_newxyz[o+1] = py; g_newxyz[o+2] = pz;
            if (write_tail){ out_tail[o] = px; out_tail[o+1] = py; out_tail[o+2] = pz; }
        }
        unsigned long long key[8];
        #pragma unroll
        for (int k = 0; k < 8; k++){
            float dx = rx[k] - px;
            float dy = ry[k] - py;
            float dz = rz[k] - pz;
            float d = __fadd_rn(__fadd_rn(__fmul_rn(dx,dx), __fmul_rn(dy,dy)), __fmul_rn(dz,dz));
            float dm = fminf(dmin[k], d);
            dmin[k] = dm;
            key[k] = (((unsigned long long)__float_as_uint(dm)) << 13)
                   | (unsigned)(8191 - (tid + (k << 10)));
        }
        key[0] = umax64(key[0], key[1]); key[2] = umax64(key[2], key[3]);
        key[4] = umax64(key[4], key[5]); key[6] = umax64(key[6], key[7]);
        key[0] = umax64(key[0], key[2]); key[4] = umax64(key[4], key[6]);
        unsigned long long best = umax64(key[0], key[4]);
        #pragma unroll
        for (int off = 16; off; off >>= 1)
            best = umax64(best, __shfl_down_sync(0xffffffffu, best, off));
        if (lane == 0) kv[par*32 + warp] = best;
        __syncthreads();
        unsigned long long v = kv[par*32 + lane];
        #pragma unroll
        for (int off = 16; off; off >>= 1)
            v = umax64(v, __shfl_xor_sync(0xffffffffu, v, off));
        last = 8191 - (int)(v & 0x1FFFu);
        par ^= 1;
    }
}

// ---------------- kernel 2: ball query (first NSAMP in index order) ----------------
__global__ void ballquery_kernel(const float* __restrict__ xyz){
    int q = blockIdx.x * 8 + (threadIdx.x >> 5);
    if (q >= NQ) return;
    int lane = threadIdx.x & 31;
    int b = q >> 10;
    const float* xb = xyz + (size_t)b * NPTS * 3;
    float qx = g_newxyz[q*3], qy = g_newxyz[q*3+1], qz = g_newxyz[q*3+2];
    int* g = g_gidx + q*NSAMP;
    const float RR = 0.04f;
    int count = 0;
    for (int base = 0; base < NPTS; base += 32){
        int n = base + lane;
        float dx = xb[3*n] - qx, dy = xb[3*n+1] - qy, dz = xb[3*n+2] - qz;
        float d = __fadd_rn(__fadd_rn(__fmul_rn(dx,dx), __fmul_rn(dy,dy)), __fmul_rn(dz,dz));
        bool w = d < RR;
        unsigned m = __ballot_sync(0xffffffffu, w);
        if (w){
            int slot = count + __popc(m & ((1u << lane) - 1u));
            if (slot < NSAMP) g[slot] = n;
        }
        count += __popc(m);
        if (count >= NSAMP) break;
    }
    int rem = min(count, NSAMP);
    if (lane >= rem) g[lane] = -1;
}

// ---------------- kernel 3: q-moment accumulation for BN1 ----------------
// rel (13-dim) is linear in q = (gx,gy,gz,mx,my,mz,eu), so BN1 stats only need
// the 7 first moments + 28 second moments of q over all (item,v) rows.
__global__ void __launch_bounds__(256) stats1_kernel(const float* __restrict__ xyz,
                                                     const int* __restrict__ mc_idx){
    __shared__ float smc[VNUM*3];
    __shared__ float sacc[35];
    int tid = threadIdx.x;
    int item = blockIdx.x*256 + tid;
    int b = item >> 15;
    if (tid < VNUM*3){
        int v = tid/3, c = tid - v*3;
        smc[tid] = xyz[(size_t)b*NPTS*3 + (size_t)mc_idx[v]*3 + c];
    }
    if (tid < 35) sacc[tid] = 0.f;
    __syncthreads();

    float acc[35];
    #pragma unroll
    for (int i = 0; i < 35; i++) acc[i] = 0.f;

    int gi = g_gidx[item];
    float gx = 0.f, gy = 0.f, gz = 0.f;
    if (gi >= 0){
        const float* p = xyz + (size_t)b*NPTS*3 + (size_t)gi*3;
        gx = p[0]; gy = p[1]; gz = p[2];
    }
    float q[7];
    q[0] = gx; q[1] = gy; q[2] = gz;
    for (int v = 0; v < VNUM; v++){
        q[3] = smc[v*3]; q[4] = smc[v*3+1]; q[5] = smc[v*3+2];
        float a0 = gx-q[3], a1 = gy-q[4], a2 = gz-q[5];
        q[6] = sqrtf(a0*a0 + a1*a1 + a2*a2);
        int c = 7;
        #pragma unroll
        for (int i = 0; i < 7; i++){
            acc[i] += q[i];
            #pragma unroll
            for (int j = i; j < 7; j++) acc[c++] += q[i]*q[j];
        }
    }
    #pragma unroll
    for (int off = 16; off; off >>= 1)
        #pragma unroll
        for (int i = 0; i < 35; i++)
            acc[i] += __shfl_down_sync(0xffffffffu, acc[i], off);
    if ((tid & 31) == 0)
        for (int i = 0; i < 35; i++) atomicAdd(&sacc[i], acc[i]);
    __syncthreads();
    if (tid < 35) atomicAdd(&g_q[tid], (double)sacc[tid]);
}

// ---------------- kernel 3b: reconstruct BN1 scale/shift from q-moments ----------------
__global__ void finalize_bn1(const float* __restrict__ g1, const float* __restrict__ be1,
                             const float* __restrict__ W1_0, const float* __restrict__ b1_0){
    __shared__ double sSrel[13][13];
    __shared__ double smrel[13];
    int t = threadIdx.x;
    if (t == 0){
        const double n = (double)NITEMS * (double)VNUM;
        double mq[7], Sq[7][7];
        for (int i = 0; i < 7; i++) mq[i] = g_q[i] / n;
        {
            int c = 0;
            for (int i = 0; i < 7; i++)
                for (int j = i; j < 7; j++){
                    double v = g_q[7 + c] / n; c++;
                    Sq[i][j] = v; Sq[j][i] = v;
                }
        }
        // rel_i as <=2-term linear combos of q
        int qa[13][2]; double cf[13][2]; int nt[13];
        for (int i = 0; i < 3; i++){ qa[i][0]=3+i; cf[i][0]= 1.0; qa[i][1]=i;   cf[i][1]=-1.0; nt[i]=2; }       // m-g
        for (int i = 0; i < 3; i++){ qa[3+i][0]=i; cf[3+i][0]=1.0; qa[3+i][1]=3+i; cf[3+i][1]=-1.0; nt[3+i]=2; } // g-m
        qa[6][0]=6; cf[6][0]=1.0; nt[6]=1;                                                                       // eu
        for (int i = 0; i < 3; i++){ qa[7+i][0]=i;   cf[7+i][0]=1.0;  nt[7+i]=1;  }                              // g
        for (int i = 0; i < 3; i++){ qa[10+i][0]=3+i; cf[10+i][0]=1.0; nt[10+i]=1; }                             // m
        for (int i = 0; i < 13; i++){
            double m = 0;
            for (int u = 0; u < nt[i]; u++) m += cf[i][u]*mq[qa[i][u]];
            smrel[i] = m;
        }
        for (int i = 0; i < 13; i++)
            for (int j = 0; j < 13; j++){
                double s = 0;
                for (int u = 0; u < nt[i]; u++)
                    for (int v = 0; v < nt[j]; v++)
                        s += cf[i][u]*cf[j][v]*Sq[qa[i][u]][qa[j][v]];
                sSrel[i][j] = s;
            }
    }
    __syncthreads();
    if (t < HID1){
        double w[13];
        for (int i = 0; i < 13; i++) w[i] = (double)W1_0[t*13+i];
        double bb = (double)b1_0[t];
        double wm = 0;
        for (int i = 0; i < 13; i++) wm += w[i]*smrel[i];
        double mean = wm + bb;
        double e2 = bb*bb + 2.0*bb*wm;
        for (int i = 0; i < 13; i++){
            double a = 0;
            for (int j = 0; j < 13; j++) a += w[j]*sSrel[i][j];
            e2 += w[i]*a;
        }
        double var = e2 - mean*mean;
        double sc = (double)g1[t] / sqrt(var + 1e-5);
        g_bn1[t] = (float)sc;
        g_bn1[HID1+t] = (float)((double)be1[t] - mean*sc);
    }
}

// ---------------- kernel 4: fused main (gf, MLP1, gumbel-softmax, gf2) ----------------
#define M1_W10  0      /* 416  */
#define M1_B10  416    /* 32   */
#define M1_SC   448    /* 32   */
#define M1_SH   480    /* 32   */
#define M1_W11  512    /* 2240 */
#define M1_B11  2752   /* 70   */
#define M1_GF   2824   /* 2240 */
#define M1_GX   5064   /* 96   */
#define M1_MC   5160   /* 24   */
#define M1_NEW  5184   /* 3    */
#define M1_GI   5188   /* 32 ints */
#define M1_A2   5220   /* 256*71 = 18176 */
#define M1_TOT  23396

__global__ void __launch_bounds__(256) main1_kernel(const float* __restrict__ xyz,
                                                    const float* __restrict__ f,
                                                    const int* __restrict__ mc_idx,
                                                    const float* __restrict__ gumbel,
                                                    const float* __restrict__ W1_0,
                                                    const float* __restrict__ b1_0,
                                                    const float* __restrict__ W1_1,
                                                    const float* __restrict__ b1_1){
    extern __shared__ float sm[];
    float* sW10 = sm + M1_W10;
    float* sb10 = sm + M1_B10;
    float* ssc  = sm + M1_SC;
    float* ssh  = sm + M1_SH;
    float* sW11 = sm + M1_W11;
    float* sb11 = sm + M1_B11;
    float* sgf  = sm + M1_GF;
    float* sgx  = sm + M1_GX;
    float* smc  = sm + M1_MC;
    float* snew = sm + M1_NEW;
    int*   sgi  = (int*)(sm + M1_GI);
    float* sa2  = sm + M1_A2;

    int tid = threadIdx.x;
    int bs  = blockIdx.x;
    int b   = bs >> 10;

    for (int i = tid; i < HID1*13; i += 256) sW10[i] = W1_0[i];
    for (int i = tid; i < CIN*HID1; i += 256) sW11[i] = W1_1[i];
    if (tid < 32){ sb10[tid] = b1_0[tid]; ssc[tid] = g_bn1[tid]; ssh[tid] = g_bn1[32+tid]; }
    if (tid >= 64 && tid < 64+CIN) sb11[tid-64] = b1_1[tid-64];
    if (tid >= 160 && tid < 192) sgi[tid-160] = g_gidx[bs*NSAMP + tid-160];
    if (tid >= 192 && tid < 195) snew[tid-192] = g_newxyz[bs*3 + tid-192];
    if (tid >= 200 && tid < 224){
        int j = tid - 200; int v = j/3, c = j - v*3;
        smc[j] = xyz[(size_t)b*NPTS*3 + (size_t)mc_idx[v]*3 + c];
    }
    __syncthreads();

    if (tid < 96){
        int n = tid/3, c = tid - n*3;
        int gi = sgi[n];
        sgx[tid] = (gi < 0) ? 0.0f : xyz[(size_t)b*NPTS*3 + (size_t)gi*3 + c];
    }
    __syncthreads();

    for (int idx = tid; idx < NSAMP*CIN; idx += 256){
        int n = idx / CIN, c = idx - n*CIN;
        int gi = sgi[n];
        float val;
        if (c < 3)      val = sgx[n*3 + c];
        else if (c < 6) val = sgx[n*3 + c - 3] - snew[c-3];
        else            val = (gi < 0) ? 0.0f : f[((size_t)b*NPTS + (size_t)gi)*CFEAT + (c-6)];
        sgf[idx] = val;
        g_gf[(size_t)bs*(NSAMP*CIN) + idx] = val;
    }
    __syncthreads();

    // phase C: one thread per (n,v) row
    {
        int n = tid >> 3, v = tid & 7;
        float gx = sgx[n*3], gy = sgx[n*3+1], gz = sgx[n*3+2];
        float mx = smc[v*3], my = smc[v*3+1], mz = smc[v*3+2];
        float a0 = gx-mx, a1 = gy-my, a2v = gz-mz;
        float eu = sqrtf(a0*a0 + a1*a1 + a2v*a2v);
        float rel[13] = {-a0,-a1,-a2v, a0,a1,a2v, eu, gx,gy,gz, mx,my,mz};
        float h[HID1];
        #pragma unroll
        for (int o = 0; o < HID1; o++){
            float a = sb10[o];
            #pragma unroll
            for (int i = 0; i < 13; i++) a += rel[i] * sW10[o*13+i];
            a = a * ssc[o] + ssh[o];
            h[o] = gelu_exact(a);
        }
        for (int c = 0; c < CIN; c++){
            float acc = sb11[c];
            const float4* w4 = reinterpret_cast<const float4*>(&sW11[c*HID1]);
            #pragma unroll
            for (int q8 = 0; q8 < 8; q8++){
                float4 w = w4[q8];
                acc += h[q8*4+0]*w.x + h[q8*4+1]*w.y + h[q8*4+2]*w.z + h[q8*4+3]*w.w;
            }
            sa2[tid*71 + c] = acc;
        }
    }
    __syncthreads();

    // phase D: gumbel softmax over V, aggregate, write gf2
    for (int idx = tid; idx < NSAMP*CIN; idx += 256){
        int n = idx / CIN, c = idx - n*CIN;
        float gfv = sgf[idx];
        int base = n*8*71 + c;
        float p[8];
        #pragma unroll
        for (int v = 0; v < 8; v++) p[v] = gfv * sa2[base + v*71];
        const float4* gp = reinterpret_cast<const float4*>(gumbel + ((size_t)bs*(NSAMP*CIN) + idx)*8);
        float4 u0 = gp[0], u1 = gp[1];
        float uu[8] = {u0.x,u0.y,u0.z,u0.w,u1.x,u1.y,u1.z,u1.w};
        float x[8];
        float mx = __int_as_float(0xff800000);
        #pragma unroll
        for (int v = 0; v < 8; v++){
            float gn = -__logf(neglog_u(uu[v]));
            x[v] = p[v] + gn;
            mx = fmaxf(mx, x[v]);
        }
        float se = 0.f, num = 0.f;
        #pragma unroll
        for (int v = 0; v < 8; v++){
            float e = __expf(x[v] - mx);
            se += e; num += e * p[v];
        }
        float agg = num / se;
        float outv = (sgi[n] < 0) ? 0.0f : (agg + gfv);
        g_gf2[(size_t)bs*(NSAMP*CIN) + idx] = outv;
    }
}

// ---------------- kernel 5: w_pre = gf2 @ W2_0^T + b2_0  (+ BN2 stats) ----------------
#define K5_GF2 0                    /* 64*71 = 4544 */
#define K5_WT  4544                 /* 70*132 = 9240 */
#define K5_SUM 13784                /* 128 */
#define K5_SQ  13912                /* 128 */
#define K5_TOT 14040

__global__ void __launch_bounds__(256) w_stats_kernel(const float* __restrict__ W2_0,
                                                      const float* __restrict__ b2_0){
    extern __shared__ float sm[];
    float* sG  = sm + K5_GF2;
    float* sWt = sm + K5_WT;
    float* ssum = sm + K5_SUM;
    float* ssq  = sm + K5_SQ;
    int tid = threadIdx.x;
    int row0 = blockIdx.x * 64;

    for (int idx = tid; idx < COUT*CIN; idx += 256){
        int o = idx / CIN, i = idx - o*CIN;
        sWt[i*132 + o] = W2_0[idx];
    }
    for (int idx = tid; idx < 64*CIN; idx += 256){
        int r = idx / CIN, i = idx - r*CIN;
        sG[r*71 + i] = g_gf2[(size_t)row0*CIN + idx];
    }
    if (tid < 128){ ssum[tid] = 0.f; ssq[tid] = 0.f; }
    __syncthreads();

    int rt = tid >> 5, ct = tid & 31;
    float acc[8][4];
    #pragma unroll
    for (int r = 0; r < 8; r++)
        #pragma unroll
        for (int c = 0; c < 4; c++) acc[r][c] = 0.f;

    for (int k = 0; k < CIN; k++){
        float4 w = *reinterpret_cast<const float4*>(&sWt[k*132 + ct*4]);
        #pragma unroll
        for (int r = 0; r < 8; r++){
            float g = sG[(rt*8 + r)*71 + k];
            acc[r][0] += g * w.x; acc[r][1] += g * w.y;
            acc[r][2] += g * w.z; acc[r][3] += g * w.w;
        }
    }
    float4 bb = *reinterpret_cast<const float4*>(&b2_0[ct*4]);
    float bias[4] = {bb.x, bb.y, bb.z, bb.w};
    float s[4] = {0,0,0,0}, q[4] = {0,0,0,0};
    #pragma unroll
    for (int r = 0; r < 8; r++){
        #pragma unroll
        for (int c = 0; c < 4; c++){
            acc[r][c] += bias[c];
            s[c] += acc[r][c];
            q[c] += acc[r][c]*acc[r][c];
        }
        float4 o4 = make_float4(acc[r][0], acc[r][1], acc[r][2], acc[r][3]);
        *reinterpret_cast<float4*>(&g_w[((size_t)row0 + rt*8 + r)*COUT + ct*4]) = o4;
    }
    #pragma unroll
    for (int c = 0; c < 4; c++){
        atomicAdd(&ssum[ct*4 + c], s[c]);
        atomicAdd(&ssq [ct*4 + c], q[c]);
    }
    __syncthreads();
    if (tid < 128){
        atomicAdd(&g_stats2[tid],      (double)ssum[tid]);
        atomicAdd(&g_stats2[128+tid],  (double)ssq[tid]);
    }
}

__global__ void finalize_bn2(const float* __restrict__ g2, const float* __restrict__ be2){
    int o = threadIdx.x;
    if (o < COUT){
        double n = (double)NITEMS;
        double m = g_stats2[o] / n;
        double var = g_stats2[COUT+o] / n - m*m;
        double sc = (double)g2[o] / sqrt(var + 1e-5);
        g_bn2[o] = (float)sc;
        g_bn2[COUT+o] = (float)((double)be2[o] - m*sc);
    }
}

// ---------------- kernel 6: final fused GEMM (K=198) + gelu + max/sum reduce ----------------
#define F_W2T  0                    /* 128*132 = 16896 */
#define F_WRT  16896                /* 70*132 = 9240 */
#define F_H    26136                /* 32*128 = 4096 */
#define F_GF   30232                /* 32*71  = 2272 */
#define F_BN   32504                /* 256 */
#define F_RM   32760                /* 8*128 = 1024 */
#define F_RS   33784                /* 8*128 = 1024 */
#define F_TOT  34808

__global__ void __launch_bounds__(256) final_kernel(const float* __restrict__ W2_1,
                                                    const float* __restrict__ b2_1,
                                                    const float* __restrict__ Wr,
                                                    const float* __restrict__ br,
                                                    float* __restrict__ out){
    extern __shared__ float sm[];
    float* sW2t = sm + F_W2T;
    float* sWrt = sm + F_WRT;
    float* sh   = sm + F_H;
    float* sgf  = sm + F_GF;
    float* sbn  = sm + F_BN;
    float* srm  = sm + F_RM;
    float* srs  = sm + F_RS;
    int tid = threadIdx.x;

    for (int idx = tid; idx < COUT*COUT; idx += 256){
        int o = idx >> 7, k = idx & 127;
        sW2t[k*132 + o] = W2_1[idx];
    }
    for (int idx = tid; idx < COUT*CIN; idx += 256){
        int o = idx / CIN, i = idx - o*CIN;
        sWrt[i*132 + o] = Wr[idx];
    }
    if (tid < 256) sbn[tid] = g_bn2[tid];

    int rt = tid >> 5, ct = tid & 31;
    float4 b1v = *reinterpret_cast<const float4*>(&b2_1[ct*4]);
    float4 brv = *reinterpret_cast<const float4*>(&br[ct*4]);
    float bsum[4] = {b1v.x + brv.x, b1v.y + brv.y, b1v.z + brv.z, b1v.w + brv.w};

    for (int g = 0; g < 4; g++){
        int bs = blockIdx.x*4 + g;
        __syncthreads();
        for (int idx = tid; idx < NSAMP*COUT; idx += 256){
            int o = idx & 127;
            float v = g_w[(size_t)bs*(NSAMP*COUT) + idx];
            sh[idx] = gelu_exact(v * sbn[o] + sbn[128+o]);
        }
        for (int idx = tid; idx < NSAMP*CIN; idx += 256){
            int r = idx / CIN, i = idx - r*CIN;
            sgf[r*71 + i] = g_gf[(size_t)bs*(NSAMP*CIN) + idx];
        }
        __syncthreads();

        float acc[4][4];
        #pragma unroll
        for (int r = 0; r < 4; r++)
            #pragma unroll
            for (int c = 0; c < 4; c++) acc[r][c] = bsum[c];

        for (int k = 0; k < COUT; k++){
            float4 w = *reinterpret_cast<const float4*>(&sW2t[k*132 + ct*4]);
            #pragma unroll
            for (int r = 0; r < 4; r++){
                float h = sh[(rt*4 + r)*COUT + k];
                acc[r][0] += h * w.x; acc[r][1] += h * w.y;
                acc[r][2] += h * w.z; acc[r][3] += h * w.w;
            }
        }
        for (int i = 0; i < CIN; i++){
            float4 w = *reinterpret_cast<const float4*>(&sWrt[i*132 + ct*4]);
            #pragma unroll
            for (int r = 0; r < 4; r++){
                float gv = sgf[(rt*4 + r)*71 + i];
                acc[r][0] += gv * w.x; acc[r][1] += gv * w.y;
                acc[r][2] += gv * w.z; acc[r][3] += gv * w.w;
            }
        }
        float mxv[4], smv[4];
        #pragma unroll
        for (int c = 0; c < 4; c++){ mxv[c] = __int_as_float(0xff800000); smv[c] = 0.f; }
        #pragma unroll
        for (int r = 0; r < 4; r++)
            #pragma unroll
            for (int c = 0; c < 4; c++){
                float nf = gelu_exact(acc[r][c]);
                mxv[c] = fmaxf(mxv[c], nf);
                smv[c] += nf;
            }
        #pragma unroll
        for (int c = 0; c < 4; c++){
            srm[rt*128 + ct*4 + c] = mxv[c];
            srs[rt*128 + ct*4 + c] = smv[c];
        }
        __syncthreads();
        if (tid < 128){
            float m = srm[tid], s = srs[tid];
            #pragma unroll
            for (int w = 1; w < 8; w++){
                m = fmaxf(m, srm[w*128 + tid]);
                s += srs[w*128 + tid];
            }
            out[(size_t)bs*COUT + tid] = m + s;
        }
    }
}

// ---------------- launch ----------------
extern "C" void kernel_launch(void* const* d_in, const int* in_sizes, int n_in,
                              void* d_out, int out_size) {
    const float* xyz    = (const float*)d_in[0];
    const float* f      = (const float*)d_in[1];
    const int*   mc_idx = (const int*)  d_in[2];
    const float* gumbel = (const float*)d_in[3];
    const float* W1_0   = (const float*)d_in[4];
    const float* b1_0   = (const float*)d_in[5];
    const float* g1_0   = (const float*)d_in[6];
    const float* be1_0  = (const float*)d_in[7];
    const float* W1_1   = (const float*)d_in[8];
    const float* b1_1   = (const float*)d_in[9];
    const float* W2_0   = (const float*)d_in[10];
    const float* b2_0   = (const float*)d_in[11];
    const float* g2_0   = (const float*)d_in[12];
    const float* be2_0  = (const float*)d_in[13];
    const float* W2_1   = (const float*)d_in[14];
    const float* b2_1   = (const float*)d_in[15];
    const float* Wr     = (const float*)d_in[16];
    const float* br     = (const float*)d_in[17];
    float* out = (float*)d_out;

    const int fps_smem = 3*NPTS*4 + 64*8;            // 98816
    const int m1_smem  = M1_TOT * 4;                 // 93584
    const int k5_smem  = K5_TOT * 4;                 // 56160
    const int fi_smem  = F_TOT * 4;                  // 139232
    cudaFuncSetAttribute(fps_kernel,    cudaFuncAttributeMaxDynamicSharedMemorySize, fps_smem);
    cudaFuncSetAttribute(main1_kernel,  cudaFuncAttributeMaxDynamicSharedMemorySize, m1_smem);
    cudaFuncSetAttribute(w_stats_kernel,cudaFuncAttributeMaxDynamicSharedMemorySize, k5_smem);
    cudaFuncSetAttribute(final_kernel,  cudaFuncAttributeMaxDynamicSharedMemorySize, fi_smem);

    int write_tail = (out_size >= NQ*COUT + NQ*3) ? 1 : 0;
    float* tail = out + (size_t)NQ*COUT;

    zero_stats_kernel<<<1, 256>>>();
    fps_kernel<<<BATCH, 1024, fps_smem>>>(xyz, tail, write_tail);
    ballquery_kernel<<<NQ/8, 256>>>(xyz);
    stats1_kernel<<<NITEMS/256, 256>>>(xyz, mc_idx);
    finalize_bn1<<<1, 128>>>(g1_0, be1_0, W1_0, b1_0);
    main1_kernel<<<NQ, 256, m1_smem>>>(xyz, f, mc_idx, gumbel, W1_0, b1_0, W1_1, b1_1);
    w_stats_kernel<<<NITEMS/64, 256, k5_smem>>>(W2_0, b2_0);
    finalize_bn2<<<1, 128>>>(g2_0, be2_0);
    final_kernel<<<NQ/4, 256, fi_smem>>>(W2_1, b2_1, Wr, br, out);
}

// round 10
// speedup vs baseline: 1.5825x; 1.5420x over previous
#include <cuda_runtime.h>
#include <cstdint>
#include <cstddef>

#define BATCH 2
#define NPTS  8192
#define SPTS  1024
#define NSAMP 32
#define VNUM  8
#define CFEAT 64
#define CIN   70
#define COUT  128
#define HID1  32
#define NQ     (BATCH*SPTS)        /* 2048  */
#define NITEMS (NQ*NSAMP)          /* 65536 */

// ---------------- static device scratch ----------------
__device__ __align__(16) float g_newxyz[NQ*3];
__device__ __align__(16) int   g_gidx[NITEMS];
__device__ __align__(16) float g_gf [NITEMS*CIN];   // 18.3 MB
__device__ __align__(16) float g_gf2[NITEMS*CIN];   // 18.3 MB
__device__ __align__(16) float g_w  [NITEMS*COUT];  // 33.5 MB
__device__ double g_q[35];          // q-moment sums (7 first + 28 second)
__device__ double g_stats2[2*COUT];
__device__ float  g_bn1[2*HID1];
__device__ float  g_bn2[2*COUT];

__device__ __forceinline__ float gelu_exact(float x){
    return 0.5f * x * (1.0f + erff(x * 0.70710678118654752440f));
}
// -log(u) with MUFU log, series-guarded near u=1.
__device__ __forceinline__ float neglog_u(float u){
    float t = 1.0f - u;
    float y = -__logf(u);
    if (t < 0.0078125f) y = t*(1.0f + t*(0.5f + t*0.3333333333f));
    return y;
}

// ---- packed f32x2 helpers (per-lane IEEE rn => bitwise == scalar __fadd_rn/__fmul_rn) ----
__device__ __forceinline__ unsigned long long f2_pack(float lo, float hi){
    unsigned long long r;
    asm("mov.b64 %0, {%1, %2};" : "=l"(r) : "f"(lo), "f"(hi));
    return r;
}
__device__ __forceinline__ void f2_unpack(float& lo, float& hi, unsigned long long v){
    asm("mov.b64 {%0, %1}, %2;" : "=f"(lo), "=f"(hi) : "l"(v));
}
__device__ __forceinline__ unsigned long long f2_add(unsigned long long a, unsigned long long b){
    unsigned long long r;
    asm("add.rn.f32x2 %0, %1, %2;" : "=l"(r) : "l"(a), "l"(b));
    return r;
}
__device__ __forceinline__ unsigned long long f2_mul(unsigned long long a, unsigned long long b){
    unsigned long long r;
    asm("mul.rn.f32x2 %0, %1, %2;" : "=l"(r) : "l"(a), "l"(b));
    return r;
}

// ---------------- kernel 0: zero stats ----------------
__global__ void zero_stats_kernel(){
    int t = threadIdx.x;
    if (t < 35) g_q[t] = 0.0;
    g_stats2[t] = 0.0;               // blockDim = 256 = 2*COUT
}

// ---------------- kernel 1: farthest point sampling ----------------
// One block per batch. Coords in packed f32x2 registers (no spills), dmin in
// registers, REDUX-based exact argmax (value max + lowest-index tie-break),
// one barrier per step via parity-double-buffered partials.
__global__ void __launch_bounds__(1024) fps_kernel(const float* __restrict__ xyz,
                                                   float* __restrict__ out_tail,
                                                   int write_tail){
    int b = blockIdx.x;
    extern __shared__ float sm[];
    float* sx = sm;
    float* sy = sm + NPTS;
    float* sz = sm + 2*NPTS;
    unsigned* sval = (unsigned*)(sm + 3*NPTS);   // 2 x 32
    unsigned* sidx = sval + 64;                  // 2 x 32

    const float* xb = xyz + (size_t)b * NPTS * 3;
    int tid = threadIdx.x;
    for (int i = tid; i < NPTS; i += 1024){
        sx[i] = xb[3*i]; sy[i] = xb[3*i+1]; sz[i] = xb[3*i+2];
    }
    __syncthreads();

    // pack 8 points/thread into 4 f32x2 pairs per coordinate
    unsigned long long rx2[4], ry2[4], rz2[4];
    float dmin[8];
    #pragma unroll
    for (int j = 0; j < 4; j++){
        int n0 = tid + ((2*j)   << 10);
        int n1 = tid + ((2*j+1) << 10);
        rx2[j] = f2_pack(sx[n0], sx[n1]);
        ry2[j] = f2_pack(sy[n0], sy[n1]);
        rz2[j] = f2_pack(sz[n0], sz[n1]);
        dmin[2*j]   = __int_as_float(0x7f800000);
        dmin[2*j+1] = __int_as_float(0x7f800000);
    }
    int last = 0;
    int lane = tid & 31, warp = tid >> 5;
    int par = 0;

    for (int s = 0; s < SPTS; s++){
        float px = sx[last], py = sy[last], pz = sz[last];
        if (tid == 0){
            int o = (b*SPTS + s)*3;
            g_newxyz[o] = px; g_newxyz[o+1] = py; g_newxyz[o+2] = pz;
            if (write_tail){ out_tail[o] = px; out_tail[o+1] = py; out_tail[o+2] = pz; }
        }
        unsigned long long npx2 = f2_pack(-px, -px);
        unsigned long long npy2 = f2_pack(-py, -py);
        unsigned long long npz2 = f2_pack(-pz, -pz);
        #pragma unroll
        for (int j = 0; j < 4; j++){
            unsigned long long dx = f2_add(rx2[j], npx2);
            unsigned long long dy = f2_add(ry2[j], npy2);
            unsigned long long dz = f2_add(rz2[j], npz2);
            unsigned long long d2 = f2_add(f2_add(f2_mul(dx,dx), f2_mul(dy,dy)), f2_mul(dz,dz));
            float d0, d1; f2_unpack(d0, d1, d2);
            dmin[2*j]   = fminf(dmin[2*j],   d0);
            dmin[2*j+1] = fminf(dmin[2*j+1], d1);
        }
        // intra-thread value max + lowest-k tie-break
        float mx = dmin[0];
        #pragma unroll
        for (int k = 1; k < 8; k++) mx = fmaxf(mx, dmin[k]);
        int kb = 7;
        #pragma unroll
        for (int k = 6; k >= 0; k--) kb = (dmin[k] == mx) ? k : kb;
        unsigned nb = (unsigned)(tid + (kb << 10));
        // intra-warp: REDUX on value bits (dmin>=0 -> uint order == float order)
        unsigned vb   = __float_as_uint(mx);
        unsigned wmax = __reduce_max_sync(0xffffffffu, vb);
        unsigned cand = (vb == wmax) ? nb : 0xffffu;
        unsigned widx = __reduce_min_sync(0xffffffffu, cand);
        if (lane == 0){ sval[par*32 + warp] = wmax; sidx[par*32 + warp] = widx; }
        __syncthreads();
        // every warp redundantly reduces the 32 partials (no 2nd barrier)
        unsigned v2 = sval[par*32 + lane];
        unsigned i2 = sidx[par*32 + lane];
        unsigned m2 = __reduce_max_sync(0xffffffffu, v2);
        unsigned c2 = (v2 == m2) ? i2 : 0xffffu;
        last = (int)__reduce_min_sync(0xffffffffu, c2);
        par ^= 1;
    }
}

// ---------------- kernel 2: ball query (first NSAMP in index order) ----------------
__global__ void ballquery_kernel(const float* __restrict__ xyz){
    int q = blockIdx.x * 8 + (threadIdx.x >> 5);
    if (q >= NQ) return;
    int lane = threadIdx.x & 31;
    int b = q >> 10;
    const float* xb = xyz + (size_t)b * NPTS * 3;
    float qx = g_newxyz[q*3], qy = g_newxyz[q*3+1], qz = g_newxyz[q*3+2];
    int* g = g_gidx + q*NSAMP;
    const float RR = 0.04f;
    int count = 0;
    for (int base = 0; base < NPTS; base += 32){
        int n = base + lane;
        float dx = xb[3*n] - qx, dy = xb[3*n+1] - qy, dz = xb[3*n+2] - qz;
        float d = __fadd_rn(__fadd_rn(__fmul_rn(dx,dx), __fmul_rn(dy,dy)), __fmul_rn(dz,dz));
        bool w = d < RR;
        unsigned m = __ballot_sync(0xffffffffu, w);
        if (w){
            int slot = count + __popc(m & ((1u << lane) - 1u));
            if (slot < NSAMP) g[slot] = n;
        }
        count += __popc(m);
        if (count >= NSAMP) break;
    }
    int rem = min(count, NSAMP);
    if (lane >= rem) g[lane] = -1;
}

// ---------------- kernel 3: q-moment accumulation for BN1 ----------------
__global__ void __launch_bounds__(256) stats1_kernel(const float* __restrict__ xyz,
                                                     const int* __restrict__ mc_idx){
    __shared__ float smc[VNUM*3];
    __shared__ float sacc[35];
    int tid = threadIdx.x;
    int item = blockIdx.x*256 + tid;
    int b = item >> 15;
    if (tid < VNUM*3){
        int v = tid/3, c = tid - v*3;
        smc[tid] = xyz[(size_t)b*NPTS*3 + (size_t)mc_idx[v]*3 + c];
    }
    if (tid < 35) sacc[tid] = 0.f;
    __syncthreads();

    float acc[35];
    #pragma unroll
    for (int i = 0; i < 35; i++) acc[i] = 0.f;

    int gi = g_gidx[item];
    float gx = 0.f, gy = 0.f, gz = 0.f;
    if (gi >= 0){
        const float* p = xyz + (size_t)b*NPTS*3 + (size_t)gi*3;
        gx = p[0]; gy = p[1]; gz = p[2];
    }
    float q[7];
    q[0] = gx; q[1] = gy; q[2] = gz;
    for (int v = 0; v < VNUM; v++){
        q[3] = smc[v*3]; q[4] = smc[v*3+1]; q[5] = smc[v*3+2];
        float a0 = gx-q[3], a1 = gy-q[4], a2 = gz-q[5];
        q[6] = sqrtf(a0*a0 + a1*a1 + a2*a2);
        int c = 7;
        #pragma unroll
        for (int i = 0; i < 7; i++){
            acc[i] += q[i];
            #pragma unroll
            for (int j = i; j < 7; j++) acc[c++] += q[i]*q[j];
        }
    }
    #pragma unroll
    for (int off = 16; off; off >>= 1)
        #pragma unroll
        for (int i = 0; i < 35; i++)
            acc[i] += __shfl_down_sync(0xffffffffu, acc[i], off);
    if ((tid & 31) == 0)
        for (int i = 0; i < 35; i++) atomicAdd(&sacc[i], acc[i]);
    __syncthreads();
    if (tid < 35) atomicAdd(&g_q[tid], (double)sacc[tid]);
}

// ---------------- kernel 3b: reconstruct BN1 scale/shift from q-moments ----------------
__global__ void finalize_bn1(const float* __restrict__ g1, const float* __restrict__ be1,
                             const float* __restrict__ W1_0, const float* __restrict__ b1_0){
    __shared__ double sSrel[13][13];
    __shared__ double smrel[13];
    int t = threadIdx.x;
    if (t == 0){
        const double n = (double)NITEMS * (double)VNUM;
        double mq[7], Sq[7][7];
        for (int i = 0; i < 7; i++) mq[i] = g_q[i] / n;
        {
            int c = 0;
            for (int i = 0; i < 7; i++)
                for (int j = i; j < 7; j++){
                    double v = g_q[7 + c] / n; c++;
                    Sq[i][j] = v; Sq[j][i] = v;
                }
        }
        int qa[13][2]; double cf[13][2]; int nt[13];
        for (int i = 0; i < 3; i++){ qa[i][0]=3+i; cf[i][0]= 1.0; qa[i][1]=i;   cf[i][1]=-1.0; nt[i]=2; }
        for (int i = 0; i < 3; i++){ qa[3+i][0]=i; cf[3+i][0]=1.0; qa[3+i][1]=3+i; cf[3+i][1]=-1.0; nt[3+i]=2; }
        qa[6][0]=6; cf[6][0]=1.0; nt[6]=1;
        for (int i = 0; i < 3; i++){ qa[7+i][0]=i;   cf[7+i][0]=1.0;  nt[7+i]=1;  }
        for (int i = 0; i < 3; i++){ qa[10+i][0]=3+i; cf[10+i][0]=1.0; nt[10+i]=1; }
        for (int i = 0; i < 13; i++){
            double m = 0;
            for (int u = 0; u < nt[i]; u++) m += cf[i][u]*mq[qa[i][u]];
            smrel[i] = m;
        }
        for (int i = 0; i < 13; i++)
            for (int j = 0; j < 13; j++){
                double s = 0;
                for (int u = 0; u < nt[i]; u++)
                    for (int v = 0; v < nt[j]; v++)
                        s += cf[i][u]*cf[j][v]*Sq[qa[i][u]][qa[j][v]];
                sSrel[i][j] = s;
            }
    }
    __syncthreads();
    if (t < HID1){
        double w[13];
        for (int i = 0; i < 13; i++) w[i] = (double)W1_0[t*13+i];
        double bb = (double)b1_0[t];
        double wm = 0;
        for (int i = 0; i < 13; i++) wm += w[i]*smrel[i];
        double mean = wm + bb;
        double e2 = bb*bb + 2.0*bb*wm;
        for (int i = 0; i < 13; i++){
            double a = 0;
            for (int j = 0; j < 13; j++) a += w[j]*sSrel[i][j];
            e2 += w[i]*a;
        }
        double var = e2 - mean*mean;
        double sc = (double)g1[t] / sqrt(var + 1e-5);
        g_bn1[t] = (float)sc;
        g_bn1[HID1+t] = (float)((double)be1[t] - mean*sc);
    }
}

// ---------------- kernel 4: fused main (gf, MLP1, gumbel-softmax, gf2) ----------------
#define M1_W10  0      /* 416  */
#define M1_B10  416    /* 32   */
#define M1_SC   448    /* 32   */
#define M1_SH   480    /* 32   */
#define M1_W11  512    /* 2240 */
#define M1_B11  2752   /* 70   */
#define M1_GF   2824   /* 2240 */
#define M1_GX   5064   /* 96   */
#define M1_MC   5160   /* 24   */
#define M1_NEW  5184   /* 3    */
#define M1_GI   5188   /* 32 ints */
#define M1_A2   5220   /* 256*71 = 18176 */
#define M1_TOT  23396

__global__ void __launch_bounds__(256) main1_kernel(const float* __restrict__ xyz,
                                                    const float* __restrict__ f,
                                                    const int* __restrict__ mc_idx,
                                                    const float* __restrict__ gumbel,
                                                    const float* __restrict__ W1_0,
                                                    const float* __restrict__ b1_0,
                                                    const float* __restrict__ W1_1,
                                                    const float* __restrict__ b1_1){
    extern __shared__ float sm[];
    float* sW10 = sm + M1_W10;
    float* sb10 = sm + M1_B10;
    float* ssc  = sm + M1_SC;
    float* ssh  = sm + M1_SH;
    float* sW11 = sm + M1_W11;
    float* sb11 = sm + M1_B11;
    float* sgf  = sm + M1_GF;
    float* sgx  = sm + M1_GX;
    float* smc  = sm + M1_MC;
    float* snew = sm + M1_NEW;
    int*   sgi  = (int*)(sm + M1_GI);
    float* sa2  = sm + M1_A2;

    int tid = threadIdx.x;
    int bs  = blockIdx.x;
    int b   = bs >> 10;

    for (int i = tid; i < HID1*13; i += 256) sW10[i] = W1_0[i];
    for (int i = tid; i < CIN*HID1; i += 256) sW11[i] = W1_1[i];
    if (tid < 32){ sb10[tid] = b1_0[tid]; ssc[tid] = g_bn1[tid]; ssh[tid] = g_bn1[32+tid]; }
    if (tid >= 64 && tid < 64+CIN) sb11[tid-64] = b1_1[tid-64];
    if (tid >= 160 && tid < 192) sgi[tid-160] = g_gidx[bs*NSAMP + tid-160];
    if (tid >= 192 && tid < 195) snew[tid-192] = g_newxyz[bs*3 + tid-192];
    if (tid >= 200 && tid < 224){
        int j = tid - 200; int v = j/3, c = j - v*3;
        smc[j] = xyz[(size_t)b*NPTS*3 + (size_t)mc_idx[v]*3 + c];
    }
    __syncthreads();

    if (tid < 96){
        int n = tid/3, c = tid - n*3;
        int gi = sgi[n];
        sgx[tid] = (gi < 0) ? 0.0f : xyz[(size_t)b*NPTS*3 + (size_t)gi*3 + c];
    }
    __syncthreads();

    for (int idx = tid; idx < NSAMP*CIN; idx += 256){
        int n = idx / CIN, c = idx - n*CIN;
        int gi = sgi[n];
        float val;
        if (c < 3)      val = sgx[n*3 + c];
        else if (c < 6) val = sgx[n*3 + c - 3] - snew[c-3];
        else            val = (gi < 0) ? 0.0f : f[((size_t)b*NPTS + (size_t)gi)*CFEAT + (c-6)];
        sgf[idx] = val;
        g_gf[(size_t)bs*(NSAMP*CIN) + idx] = val;
    }
    __syncthreads();

    // phase C: one thread per (n,v) row
    {
        int n = tid >> 3, v = tid & 7;
        float gx = sgx[n*3], gy = sgx[n*3+1], gz = sgx[n*3+2];
        float mx = smc[v*3], my = smc[v*3+1], mz = smc[v*3+2];
        float a0 = gx-mx, a1 = gy-my, a2v = gz-mz;
        float eu = sqrtf(a0*a0 + a1*a1 + a2v*a2v);
        float rel[13] = {-a0,-a1,-a2v, a0,a1,a2v, eu, gx,gy,gz, mx,my,mz};
        float h[HID1];
        #pragma unroll
        for (int o = 0; o < HID1; o++){
            float a = sb10[o];
            #pragma unroll
            for (int i = 0; i < 13; i++) a += rel[i] * sW10[o*13+i];
            a = a * ssc[o] + ssh[o];
            h[o] = gelu_exact(a);
        }
        for (int c = 0; c < CIN; c++){
            float acc = sb11[c];
            const float4* w4 = reinterpret_cast<const float4*>(&sW11[c*HID1]);
            #pragma unroll
            for (int q8 = 0; q8 < 8; q8++){
                float4 w = w4[q8];
                acc += h[q8*4+0]*w.x + h[q8*4+1]*w.y + h[q8*4+2]*w.z + h[q8*4+3]*w.w;
            }
            sa2[tid*71 + c] = acc;
        }
    }
    __syncthreads();

    // phase D: gumbel softmax over V, aggregate, write gf2
    for (int idx = tid; idx < NSAMP*CIN; idx += 256){
        int n = idx / CIN, c = idx - n*CIN;
        float gfv = sgf[idx];
        int base = n*8*71 + c;
        float p[8];
        #pragma unroll
        for (int v = 0; v < 8; v++) p[v] = gfv * sa2[base + v*71];
        const float4* gp = reinterpret_cast<const float4*>(gumbel + ((size_t)bs*(NSAMP*CIN) + idx)*8);
        float4 u0 = gp[0], u1 = gp[1];
        float uu[8] = {u0.x,u0.y,u0.z,u0.w,u1.x,u1.y,u1.z,u1.w};
        float x[8];
        float mx = __int_as_float(0xff800000);
        #pragma unroll
        for (int v = 0; v < 8; v++){
            float gn = -__logf(neglog_u(uu[v]));
            x[v] = p[v] + gn;
            mx = fmaxf(mx, x[v]);
        }
        float se = 0.f, num = 0.f;
        #pragma unroll
        for (int v = 0; v < 8; v++){
            float e = __expf(x[v] - mx);
            se += e; num += e * p[v];
        }
        float agg = num / se;
        float outv = (sgi[n] < 0) ? 0.0f : (agg + gfv);
        g_gf2[(size_t)bs*(NSAMP*CIN) + idx] = outv;
    }
}

// ---------------- kernel 5: w_pre = gf2 @ W2_0^T + b2_0  (+ BN2 stats) ----------------
#define K5_GF2 0                    /* 64*71 = 4544 */
#define K5_WT  4544                 /* 70*132 = 9240 */
#define K5_SUM 13784                /* 128 */
#define K5_SQ  13912                /* 128 */
#define K5_TOT 14040

__global__ void __launch_bounds__(256) w_stats_kernel(const float* __restrict__ W2_0,
                                                      const float* __restrict__ b2_0){
    extern __shared__ float sm[];
    float* sG  = sm + K5_GF2;
    float* sWt = sm + K5_WT;
    float* ssum = sm + K5_SUM;
    float* ssq  = sm + K5_SQ;
    int tid = threadIdx.x;
    int row0 = blockIdx.x * 64;

    for (int idx = tid; idx < COUT*CIN; idx += 256){
        int o = idx / CIN, i = idx - o*CIN;
        sWt[i*132 + o] = W2_0[idx];
    }
    for (int idx = tid; idx < 64*CIN; idx += 256){
        int r = idx / CIN, i = idx - r*CIN;
        sG[r*71 + i] = g_gf2[(size_t)row0*CIN + idx];
    }
    if (tid < 128){ ssum[tid] = 0.f; ssq[tid] = 0.f; }
    __syncthreads();

    int rt = tid >> 5, ct = tid & 31;
    float acc[8][4];
    #pragma unroll
    for (int r = 0; r < 8; r++)
        #pragma unroll
        for (int c = 0; c < 4; c++) acc[r][c] = 0.f;

    for (int k = 0; k < CIN; k++){
        float4 w = *reinterpret_cast<const float4*>(&sWt[k*132 + ct*4]);
        #pragma unroll
        for (int r = 0; r < 8; r++){
            float g = sG[(rt*8 + r)*71 + k];
            acc[r][0] += g * w.x; acc[r][1] += g * w.y;
            acc[r][2] += g * w.z; acc[r][3] += g * w.w;
        }
    }
    float4 bb = *reinterpret_cast<const float4*>(&b2_0[ct*4]);
    float bias[4] = {bb.x, bb.y, bb.z, bb.w};
    float s[4] = {0,0,0,0}, q[4] = {0,0,0,0};
    #pragma unroll
    for (int r = 0; r < 8; r++){
        #pragma unroll
        for (int c = 0; c < 4; c++){
            acc[r][c] += bias[c];
            s[c] += acc[r][c];
            q[c] += acc[r][c]*acc[r][c];
        }
        float4 o4 = make_float4(acc[r][0], acc[r][1], acc[r][2], acc[r][3]);
        *reinterpret_cast<float4*>(&g_w[((size_t)row0 + rt*8 + r)*COUT + ct*4]) = o4;
    }
    #pragma unroll
    for (int c = 0; c < 4; c++){
        atomicAdd(&ssum[ct*4 + c], s[c]);
        atomicAdd(&ssq [ct*4 + c], q[c]);
    }
    __syncthreads();
    if (tid < 128){
        atomicAdd(&g_stats2[tid],      (double)ssum[tid]);
        atomicAdd(&g_stats2[128+tid],  (double)ssq[tid]);
    }
}

__global__ void finalize_bn2(const float* __restrict__ g2, const float* __restrict__ be2){
    int o = threadIdx.x;
    if (o < COUT){
        double n = (double)NITEMS;
        double m = g_stats2[o] / n;
        double var = g_stats2[COUT+o] / n - m*m;
        double sc = (double)g2[o] / sqrt(var + 1e-5);
        g_bn2[o] = (float)sc;
        g_bn2[COUT+o] = (float)((double)be2[o] - m*sc);
    }
}

// ---------------- kernel 6: final fused GEMM (K=198) + gelu + max/sum reduce ----------------
#define F_W2T  0                    /* 128*132 = 16896 */
#define F_WRT  16896                /* 70*132 = 9240 */
#define F_H    26136                /* 32*128 = 4096 */
#define F_GF   30232                /* 32*71  = 2272 */
#define F_BN   32504                /* 256 */
#define F_RM   32760                /* 8*128 = 1024 */
#define F_RS   33784                /* 8*128 = 1024 */
#define F_TOT  34808

__global__ void __launch_bounds__(256) final_kernel(const float* __restrict__ W2_1,
                                                    const float* __restrict__ b2_1,
                                                    const float* __restrict__ Wr,
                                                    const float* __restrict__ br,
                                                    float* __restrict__ out){
    extern __shared__ float sm[];
    float* sW2t = sm + F_W2T;
    float* sWrt = sm + F_WRT;
    float* sh   = sm + F_H;
    float* sgf  = sm + F_GF;
    float* sbn  = sm + F_BN;
    float* srm  = sm + F_RM;
    float* srs  = sm + F_RS;
    int tid = threadIdx.x;

    for (int idx = tid; idx < COUT*COUT; idx += 256){
        int o = idx >> 7, k = idx & 127;
        sW2t[k*132 + o] = W2_1[idx];
    }
    for (int idx = tid; idx < COUT*CIN; idx += 256){
        int o = idx / CIN, i = idx - o*CIN;
        sWrt[i*132 + o] = Wr[idx];
    }
    if (tid < 256) sbn[tid] = g_bn2[tid];

    int rt = tid >> 5, ct = tid & 31;
    float4 b1v = *reinterpret_cast<const float4*>(&b2_1[ct*4]);
    float4 brv = *reinterpret_cast<const float4*>(&br[ct*4]);
    float bsum[4] = {b1v.x + brv.x, b1v.y + brv.y, b1v.z + brv.z, b1v.w + brv.w};

    for (int g = 0; g < 4; g++){
        int bs = blockIdx.x*4 + g;
        __syncthreads();
        for (int idx = tid; idx < NSAMP*COUT; idx += 256){
            int o = idx & 127;
            float v = g_w[(size_t)bs*(NSAMP*COUT) + idx];
            sh[idx] = gelu_exact(v * sbn[o] + sbn[128+o]);
        }
        for (int idx = tid; idx < NSAMP*CIN; idx += 256){
            int r = idx / CIN, i = idx - r*CIN;
            sgf[r*71 + i] = g_gf[(size_t)bs*(NSAMP*CIN) + idx];
        }
        __syncthreads();

        float acc[4][4];
        #pragma unroll
        for (int r = 0; r < 4; r++)
            #pragma unroll
            for (int c = 0; c < 4; c++) acc[r][c] = bsum[c];

        for (int k = 0; k < COUT; k++){
            float4 w = *reinterpret_cast<const float4*>(&sW2t[k*132 + ct*4]);
            #pragma unroll
            for (int r = 0; r < 4; r++){
                float h = sh[(rt*4 + r)*COUT + k];
                acc[r][0] += h * w.x; acc[r][1] += h * w.y;
                acc[r][2] += h * w.z; acc[r][3] += h * w.w;
            }
        }
        for (int i = 0; i < CIN; i++){
            float4 w = *reinterpret_cast<const float4*>(&sWrt[i*132 + ct*4]);
            #pragma unroll
            for (int r = 0; r < 4; r++){
                float gv = sgf[(rt*4 + r)*71 + i];
                acc[r][0] += gv * w.x; acc[r][1] += gv * w.y;
                acc[r][2] += gv * w.z; acc[r][3] += gv * w.w;
            }
        }
        float mxv[4], smv[4];
        #pragma unroll
        for (int c = 0; c < 4; c++){ mxv[c] = __int_as_float(0xff800000); smv[c] = 0.f; }
        #pragma unroll
        for (int r = 0; r < 4; r++)
            #pragma unroll
            for (int c = 0; c < 4; c++){
                float nf = gelu_exact(acc[r][c]);
                mxv[c] = fmaxf(mxv[c], nf);
                smv[c] += nf;
            }
        #pragma unroll
        for (int c = 0; c < 4; c++){
            srm[rt*128 + ct*4 + c] = mxv[c];
            srs[rt*128 + ct*4 + c] = smv[c];
        }
        __syncthreads();
        if (tid < 128){
            float m = srm[tid], s = srs[tid];
            #pragma unroll
            for (int w = 1; w < 8; w++){
                m = fmaxf(m, srm[w*128 + tid]);
                s += srs[w*128 + tid];
            }
            out[(size_t)bs*COUT + tid] = m + s;
        }
    }
}

// ---------------- launch ----------------
extern "C" void kernel_launch(void* const* d_in, const int* in_sizes, int n_in,
                              void* d_out, int out_size) {
    const float* xyz    = (const float*)d_in[0];
    const float* f      = (const float*)d_in[1];
    const int*   mc_idx = (const int*)  d_in[2];
    const float* gumbel = (const float*)d_in[3];
    const float* W1_0   = (const float*)d_in[4];
    const float* b1_0   = (const float*)d_in[5];
    const float* g1_0   = (const float*)d_in[6];
    const float* be1_0  = (const float*)d_in[7];
    const float* W1_1   = (const float*)d_in[8];
    const float* b1_1   = (const float*)d_in[9];
    const float* W2_0   = (const float*)d_in[10];
    const float* b2_0   = (const float*)d_in[11];
    const float* g2_0   = (const float*)d_in[12];
    const float* be2_0  = (const float*)d_in[13];
    const float* W2_1   = (const float*)d_in[14];
    const float* b2_1   = (const float*)d_in[15];
    const float* Wr     = (const float*)d_in[16];
    const float* br     = (const float*)d_in[17];
    float* out = (float*)d_out;

    const int fps_smem = 3*NPTS*4 + 128*4;           // 98816
    const int m1_smem  = M1_TOT * 4;                 // 93584
    const int k5_smem  = K5_TOT * 4;                 // 56160
    const int fi_smem  = F_TOT * 4;                  // 139232
    cudaFuncSetAttribute(fps_kernel,    cudaFuncAttributeMaxDynamicSharedMemorySize, fps_smem);
    cudaFuncSetAttribute(main1_kernel,  cudaFuncAttributeMaxDynamicSharedMemorySize, m1_smem);
    cudaFuncSetAttribute(w_stats_kernel,cudaFuncAttributeMaxDynamicSharedMemorySize, k5_smem);
    cudaFuncSetAttribute(final_kernel,  cudaFuncAttributeMaxDynamicSharedMemorySize, fi_smem);

    int write_tail = (out_size >= NQ*COUT + NQ*3) ? 1 : 0;
    float* tail = out + (size_t)NQ*COUT;

    zero_stats_kernel<<<1, 256>>>();
    fps_kernel<<<BATCH, 1024, fps_smem>>>(xyz, tail, write_tail);
    ballquery_kernel<<<NQ/8, 256>>>(xyz);
    stats1_kernel<<<NITEMS/256, 256>>>(xyz, mc_idx);
    finalize_bn1<<<1, 128>>>(g1_0, be1_0, W1_0, b1_0);
    main1_kernel<<<NQ, 256, m1_smem>>>(xyz, f, mc_idx, gumbel, W1_0, b1_0, W1_1, b1_1);
    w_stats_kernel<<<NITEMS/64, 256, k5_smem>>>(W2_0, b2_0);
    finalize_bn2<<<1, 128>>>(g2_0, be2_0);
    final_kernel<<<NQ/4, 256, fi_smem>>>(W2_1, b2_1, Wr, br, out);
}